// round 13
// baseline (speedup 1.0000x reference)
#include <cuda_runtime.h>
#include <cuda_bf16.h>
#include <mma.h>
#include <cstdint>
#include <cstddef>

using namespace nvcuda;

#define SCALE 0.0625f
#define EPSLN 1e-5f

// edge_tc smem byte offsets (R6 winner layout)
#define OFF_A1H 0
#define OFF_A1L 33792
#define OFF_HH 67584
#define OFF_HL 101376
#define OFF_BH 135168
#define OFF_BL 172032
#define OFF_QS 208896
#define DSMEM 209920
#define LDA 264  // bf16 elems per row in A/H tiles
#define LDB 72   // bf16 elems per row in B stage
#define LDC 260  // f32 elems per row in Cstage (aliases B at OFF_BH)

typedef wmma::fragment<wmma::matrix_a, 16, 16, 16, __nv_bfloat16, wmma::row_major> FragA;
typedef wmma::fragment<wmma::matrix_b, 16, 16, 16, __nv_bfloat16, wmma::col_major> FragB;
typedef wmma::fragment<wmma::accumulator, 16, 16, 16, float> FragC;

// ---------------- device scratch ----------------
__device__ float d_q[131072];
__device__ float d_k[131072];
__device__ float d_v[131072];
__device__ float d_an1[131072];
__device__ unsigned short g_WeoH[65536], g_WeoL[65536];    // [256 n][256 k] row-major
__device__ unsigned short g_We1H[262144], g_We1L[262144];  // [1024][256]
__device__ unsigned short g_We2H[262144], g_We2L[262144];  // [256][1024]

__device__ __forceinline__ void split_w(float v, unsigned short* h, unsigned short* l) {
    __nv_bfloat16 hb = __float2bfloat16(v);
    *h = __bfloat16_as_ushort(hb);
    *l = __bfloat16_as_ushort(__float2bfloat16(v - __bfloat162float(hb)));
}
__device__ __forceinline__ void split_sm(char* smp, int off, int r, int c, float v) {
    __nv_bfloat16 hb = __float2bfloat16(v);
    *(unsigned short*)(smp + off + (r * LDA + c) * 2) = __bfloat16_as_ushort(hb);
    *(unsigned short*)(smp + off + 33792 + (r * LDA + c) * 2) =
        __bfloat16_as_ushort(__float2bfloat16(v - __bfloat162float(hb)));
}

// ---------------- prep: edge-weight bf16 hi/lo split only ----------------
__global__ void prep_kernel(const float* __restrict__ Weo, const float* __restrict__ We1,
                            const float* __restrict__ We2) {
    int idx = blockIdx.x * 256 + threadIdx.x;  // 262144
    if (idx < 65536) split_w(Weo[idx], &g_WeoH[idx], &g_WeoL[idx]);
    split_w(We1[idx], &g_We1H[idx], &g_We1L[idx]);
    split_w(We2[idx], &g_We2H[idx], &g_We2L[idx]);
}

// ---------------- qkv projection (row-major weights, float4) ----------------
__global__ void __launch_bounds__(256) qkv_kernel(const float* __restrict__ nodes,
                                                  const float* __restrict__ conds,
                                                  const float* __restrict__ Wqkv,
                                                  const float* __restrict__ bqkv) {
    __shared__ float x[256];
    int bi = blockIdx.x, b = bi >> 8, t = threadIdx.x;
    x[t] = nodes[bi * 256 + t] + conds[(b << 8) + t];
    __syncthreads();
    const float4* x4 = (const float4*)x;
#pragma unroll
    for (int s = 0; s < 3; s++) {
        int o = t + (s << 8);
        const float4* wr = (const float4*)(Wqkv + o * 256);
        float acc = bqkv[o];
#pragma unroll 8
        for (int c = 0; c < 64; c++) {
            float4 w = wr[c], xv = x4[c];
            acc += w.x * xv.x + w.y * xv.y + w.z * xv.z + w.w * xv.w;
        }
        float* dst = (s == 0) ? d_q : (s == 1) ? d_k : d_v;
        dst[bi * 256 + t] = acc;
    }
}

// ---------------- attn: logits (batched loads) -> softmax -> WV -> Wno -> LN1 ----------------
__global__ void __launch_bounds__(256) attn_kernel(const float* __restrict__ edges,
                                                   const float* __restrict__ nodes,
                                                   const float* __restrict__ Wno,
                                                   const float* __restrict__ bno,
                                                   const float* __restrict__ g1n,
                                                   const float* __restrict__ b1n) {
    __shared__ float qs[256];
    __shared__ float lg[8 * 256];
    __shared__ float wv[256];
    __shared__ float red[20];
    int bi = blockIdx.x, b = bi >> 8, t = threadIdx.x, w = t >> 5, lane = t & 31;
    qs[t] = d_q[bi * 256 + t] * SCALE;
    __syncthreads();
    const float* erow = edges + (size_t)bi * 65536;
    const float* kb = d_k + b * 65536;
    // logits: unroll-by-4 so 8 loads are in flight before the shuffle chains
#pragma unroll 1
    for (int j = 0; j < 256; j += 4) {
        float v0 = qs[t] * kb[(j + 0) * 256 + t] + erow[(j + 0) * 256 + t];
        float v1 = qs[t] * kb[(j + 1) * 256 + t] + erow[(j + 1) * 256 + t];
        float v2 = qs[t] * kb[(j + 2) * 256 + t] + erow[(j + 2) * 256 + t];
        float v3 = qs[t] * kb[(j + 3) * 256 + t] + erow[(j + 3) * 256 + t];
#pragma unroll
        for (int off = 16; off; off >>= 1) {
            v0 += __shfl_xor_sync(0xffffffffu, v0, off);
            v1 += __shfl_xor_sync(0xffffffffu, v1, off);
            v2 += __shfl_xor_sync(0xffffffffu, v2, off);
            v3 += __shfl_xor_sync(0xffffffffu, v3, off);
        }
        if (lane == 0) {
            lg[w * 256 + j + 0] = v0;
            lg[w * 256 + j + 1] = v1;
            lg[w * 256 + j + 2] = v2;
            lg[w * 256 + j + 3] = v3;
        }
    }
    __syncthreads();
    {   // softmax over j for head h = w
        float m = -1e30f;
        for (int j = lane; j < 256; j += 32) m = fmaxf(m, lg[w * 256 + j]);
#pragma unroll
        for (int off = 16; off; off >>= 1) m = fmaxf(m, __shfl_xor_sync(0xffffffffu, m, off));
        float s = 0.f;
        for (int j = lane; j < 256; j += 32) {
            float e = __expf(lg[w * 256 + j] - m);
            lg[w * 256 + j] = e; s += e;
        }
#pragma unroll
        for (int off = 16; off; off >>= 1) s += __shfl_xor_sync(0xffffffffu, s, off);
        float inv = 1.f / s;
        for (int j = lane; j < 256; j += 32) lg[w * 256 + j] *= inv;
    }
    __syncthreads();
    const float* vb = d_v + b * 65536;
    float acc = 0.f;
#pragma unroll 4
    for (int j = 0; j < 256; j++) acc += lg[w * 256 + j] * vb[j * 256 + t];
    wv[t] = acc;
    __syncthreads();
    float a = bno[t];
    {
        const float4* wr = (const float4*)(Wno + t * 256);
        const float4* wv4 = (const float4*)wv;
#pragma unroll 8
        for (int c = 0; c < 64; c++) {
            float4 ww = wr[c], xv = wv4[c];
            a += ww.x * xv.x + ww.y * xv.y + ww.z * xv.z + ww.w * xv.w;
        }
    }
    a += nodes[bi * 256 + t];
    float s1 = a, s2 = a * a;
#pragma unroll
    for (int off = 16; off; off >>= 1) {
        s1 += __shfl_xor_sync(0xffffffffu, s1, off);
        s2 += __shfl_xor_sync(0xffffffffu, s2, off);
    }
    if (lane == 0) { red[w] = s1; red[8 + w] = s2; }
    __syncthreads();
    if (t == 0) {
        float a1 = 0.f, a2 = 0.f;
        for (int x = 0; x < 8; x++) { a1 += red[x]; a2 += red[8 + x]; }
        float m = a1 * (1.f / 256.f);
        red[16] = m;
        red[17] = rsqrtf(a2 * (1.f / 256.f) - m * m + EPSLN);
    }
    __syncthreads();
    d_an1[bi * 256 + t] = (a - red[16]) * red[17] * g1n[t] + b1n[t];
}

// ---------------- node MLP (row-major weights, float4) ----------------
__global__ void __launch_bounds__(256) nodemlp_kernel(const float* __restrict__ Wn1,
                                                      const float* __restrict__ bn1,
                                                      const float* __restrict__ Wn2,
                                                      const float* __restrict__ bn2,
                                                      const float* __restrict__ g2n,
                                                      const float* __restrict__ b2n,
                                                      float* __restrict__ out_nodes) {
    __shared__ float a[256];
    __shared__ float h[1024];
    __shared__ float red[20];
    int bi = blockIdx.x, t = threadIdx.x, w = t >> 5, lane = t & 31;
    a[t] = d_an1[bi * 256 + t];
    __syncthreads();
    const float4* a4 = (const float4*)a;
#pragma unroll
    for (int s = 0; s < 4; s++) {
        int m = t + (s << 8);
        const float4* wr = (const float4*)(Wn1 + m * 256);
        float acc = bn1[m];
#pragma unroll 8
        for (int c = 0; c < 64; c++) {
            float4 ww = wr[c], xv = a4[c];
            acc += ww.x * xv.x + ww.y * xv.y + ww.z * xv.z + ww.w * xv.w;
        }
        h[m] = fmaxf(acc, 0.f);
    }
    __syncthreads();
    float o = bn2[t];
    {
        const float4* wr = (const float4*)(Wn2 + t * 1024);
        const float4* h4 = (const float4*)h;
#pragma unroll 8
        for (int c = 0; c < 256; c++) {
            float4 ww = wr[c], xv = h4[c];
            o += ww.x * xv.x + ww.y * xv.y + ww.z * xv.z + ww.w * xv.w;
        }
    }
    float v = o + a[t];
    float s1 = v, s2 = v * v;
#pragma unroll
    for (int off = 16; off; off >>= 1) {
        s1 += __shfl_xor_sync(0xffffffffu, s1, off);
        s2 += __shfl_xor_sync(0xffffffffu, s2, off);
    }
    if (lane == 0) { red[w] = s1; red[8 + w] = s2; }
    __syncthreads();
    if (t == 0) {
        float a1 = 0.f, a2 = 0.f;
        for (int x = 0; x < 8; x++) { a1 += red[x]; a2 += red[8 + x]; }
        float m = a1 * (1.f / 256.f);
        red[16] = m;
        red[17] = rsqrtf(a2 * (1.f / 256.f) - m * m + EPSLN);
    }
    __syncthreads();
    out_nodes[bi * 256 + t] = (v - red[16]) * red[17] * g2n[t] + b2n[t];
}

// ---------------- edge pipeline: R6 winner, byte-identical ----------------
__device__ __forceinline__ void stageB(char* smp, const unsigned short* __restrict__ WH,
                                       const unsigned short* __restrict__ WL, int wp,
                                       int kbase, int t) {
#pragma unroll
    for (int i = 0; i < 8; i++) {
        int idx = t + i * 256;
        int row = idx >> 3, seg = idx & 7;
        *((uint4*)(smp + OFF_BH + row * 144) + seg) =
            *((const uint4*)(WH + (size_t)row * wp + kbase) + seg);
        *((uint4*)(smp + OFF_BL + row * 144) + seg) =
            *((const uint4*)(WL + (size_t)row * wp + kbase) + seg);
    }
}

__device__ __forceinline__ void mma_chunk(const char* smp, int aoff, FragC acc[2][4],
                                          int mg, int ng, int kc) {
    const __nv_bfloat16* Ahi = (const __nv_bfloat16*)(smp + aoff);
    const __nv_bfloat16* Alo = (const __nv_bfloat16*)(smp + aoff + 33792);
    const __nv_bfloat16* Bhi = (const __nv_bfloat16*)(smp + OFF_BH);
    const __nv_bfloat16* Blo = (const __nv_bfloat16*)(smp + OFF_BL);
#pragma unroll
    for (int ks = 0; ks < 4; ks++) {
        int col = kc * 64 + ks * 16;
        FragA ah[2], al[2];
#pragma unroll
        for (int mi = 0; mi < 2; mi++) {
            int row0 = mg * 32 + mi * 16;
            wmma::load_matrix_sync(ah[mi], Ahi + row0 * LDA + col, LDA);
            wmma::load_matrix_sync(al[mi], Alo + row0 * LDA + col, LDA);
        }
#pragma unroll
        for (int ns = 0; ns < 4; ns++) {
            int n0 = ng * 64 + ns * 16;
            FragB bh, bl;
            wmma::load_matrix_sync(bh, Bhi + n0 * LDB + ks * 16, LDB);
            wmma::load_matrix_sync(bl, Blo + n0 * LDB + ks * 16, LDB);
#pragma unroll
            for (int mi = 0; mi < 2; mi++) {
                wmma::mma_sync(acc[mi][ns], ah[mi], bh, acc[mi][ns]);
                wmma::mma_sync(acc[mi][ns], ah[mi], bl, acc[mi][ns]);
                wmma::mma_sync(acc[mi][ns], al[mi], bh, acc[mi][ns]);
            }
        }
    }
}

__device__ __forceinline__ void storeC(char* smp, FragC acc[2][4], int mg, int ng) {
    float* C = (float*)(smp + OFF_BH);
#pragma unroll
    for (int mi = 0; mi < 2; mi++)
#pragma unroll
        for (int ns = 0; ns < 4; ns++)
            wmma::store_matrix_sync(C + (mg * 32 + mi * 16) * LDC + ng * 64 + ns * 16,
                                    acc[mi][ns], LDC, wmma::mem_row_major);
}

__global__ void __launch_bounds__(256) edge_tc(const float* __restrict__ edges,
                                               const float* __restrict__ beo,
                                               const float* __restrict__ g1e,
                                               const float* __restrict__ b1e,
                                               const float* __restrict__ be1,
                                               const float* __restrict__ be2,
                                               const float* __restrict__ g2e,
                                               const float* __restrict__ b2e,
                                               float* __restrict__ out_edges) {
    extern __shared__ char smp[];
    const int t = threadIdx.x, w = t >> 5;
    const int mg = w >> 2, ng = w & 3;
    const int blk = blockIdx.x;           // 0..2047, 64 rows each
    const int bi = blk >> 2;              // b*256+i
    const int b = bi >> 8;
    const int j0 = (blk & 3) << 6;
    const size_t rowbase = (size_t)blk * 64;
    const int r = t >> 2, sub = t & 3;    // epilogue mapping: 4 threads/row
    float* Cst = (float*)(smp + OFF_BH);

    // ---- T = q*k*scale + e -> split into A1 tiles ----
    float* qs = (float*)(smp + OFF_QS);
    qs[t] = d_q[bi * 256 + t];
    __syncthreads();
    const float* ebase = edges + rowbase * 256;
    const float* kbase = d_k + ((size_t)(b << 8) + j0) * 256;
#pragma unroll 4
    for (int idx = t; idx < 16384; idx += 256) {
        int rr = idx >> 8, c = idx & 255;
        split_sm(smp, OFF_A1H, rr, c, qs[c] * SCALE * kbase[idx] + ebase[idx]);
    }

    // ---- G1: C = T @ Weo^T ----
    FragC acc1[2][4];
#pragma unroll
    for (int mi = 0; mi < 2; mi++)
#pragma unroll
        for (int ns = 0; ns < 4; ns++) wmma::fill_fragment(acc1[mi][ns], 0.f);
    for (int kc = 0; kc < 4; kc++) {
        __syncthreads();
        stageB(smp, g_WeoH, g_WeoL, 256, kc * 64, t);
        __syncthreads();
        mma_chunk(smp, OFF_A1H, acc1, mg, ng, kc);
    }
    __syncthreads();
    storeC(smp, acc1, mg, ng);
    __syncthreads();

    // ---- Epi1: v = relu(C+beo)+e ; LN -> A1 ----
    {
        float s1 = 0.f, s2 = 0.f;
        const float* erow = edges + (rowbase + r) * 256;
        float* Crow = Cst + r * LDC;
#pragma unroll 4
        for (int i = 0; i < 64; i++) {
            int c = sub * 64 + i;
            float v = fmaxf(Crow[c] + beo[c], 0.f) + erow[c];
            Crow[c] = v; s1 += v; s2 += v * v;
        }
        s1 += __shfl_xor_sync(0xffffffffu, s1, 1); s2 += __shfl_xor_sync(0xffffffffu, s2, 1);
        s1 += __shfl_xor_sync(0xffffffffu, s1, 2); s2 += __shfl_xor_sync(0xffffffffu, s2, 2);
        float m = s1 * (1.f / 256.f);
        float rs = rsqrtf(s2 * (1.f / 256.f) - m * m + EPSLN);
#pragma unroll 4
        for (int i = 0; i < 64; i++) {
            int c = sub * 64 + i;
            split_sm(smp, OFF_A1H, r, c, (Crow[c] - m) * rs * g1e[c] + b1e[c]);
        }
    }

    // ---- MLP: 4 hidden chunks: G2 -> relu -> G3 accumulate ----
    FragC acc3[2][4];
#pragma unroll
    for (int mi = 0; mi < 2; mi++)
#pragma unroll
        for (int ns = 0; ns < 4; ns++) wmma::fill_fragment(acc3[mi][ns], 0.f);

    for (int nc = 0; nc < 4; nc++) {
        FragC acc2[2][4];
#pragma unroll
        for (int mi = 0; mi < 2; mi++)
#pragma unroll
            for (int ns = 0; ns < 4; ns++) wmma::fill_fragment(acc2[mi][ns], 0.f);
        for (int kc = 0; kc < 4; kc++) {
            __syncthreads();
            stageB(smp, g_We1H + nc * 65536, g_We1L + nc * 65536, 256, kc * 64, t);
            __syncthreads();
            mma_chunk(smp, OFF_A1H, acc2, mg, ng, kc);
        }
        __syncthreads();
        storeC(smp, acc2, mg, ng);
        __syncthreads();
        {   // Epi-H: H = relu(C + be1[nc*256+c])
            float* Crow = Cst + r * LDC;
#pragma unroll 4
            for (int i = 0; i < 64; i++) {
                int c = sub * 64 + i;
                split_sm(smp, OFF_HH, r, c, fmaxf(Crow[c] + be1[nc * 256 + c], 0.f));
            }
        }
        for (int kc = 0; kc < 4; kc++) {
            __syncthreads();
            stageB(smp, g_We2H, g_We2L, 1024, nc * 256 + kc * 64, t);
            __syncthreads();
            mma_chunk(smp, OFF_HH, acc3, mg, ng, kc);
        }
    }
    __syncthreads();
    storeC(smp, acc3, mg, ng);
    __syncthreads();

    // ---- Epi3: v = C + be2 + A1 ; LN -> out ----
    {
        float s1 = 0.f, s2 = 0.f;
        float* Crow = Cst + r * LDC;
        const unsigned short* a1h = (const unsigned short*)(smp + OFF_A1H) + r * LDA;
        const unsigned short* a1l = (const unsigned short*)(smp + OFF_A1L) + r * LDA;
#pragma unroll 4
        for (int i = 0; i < 64; i++) {
            int c = sub * 64 + i;
            float a1 = __bfloat162float(__ushort_as_bfloat16(a1h[c])) +
                       __bfloat162float(__ushort_as_bfloat16(a1l[c]));
            float v = Crow[c] + be2[c] + a1;
            Crow[c] = v; s1 += v; s2 += v * v;
        }
        s1 += __shfl_xor_sync(0xffffffffu, s1, 1); s2 += __shfl_xor_sync(0xffffffffu, s2, 1);
        s1 += __shfl_xor_sync(0xffffffffu, s1, 2); s2 += __shfl_xor_sync(0xffffffffu, s2, 2);
        float m = s1 * (1.f / 256.f);
        float rs = rsqrtf(s2 * (1.f / 256.f) - m * m + EPSLN);
        float* orow = out_edges + (rowbase + r) * 256;
#pragma unroll 4
        for (int i = 0; i < 64; i++) {
            int c = sub * 64 + i;
            orow[c] = (Crow[c] - m) * rs * g2e[c] + b2e[c];
        }
    }
}

__global__ void copy_conds(const float* __restrict__ conds, float* __restrict__ dst) {
    int t = blockIdx.x * 256 + threadIdx.x;
    if (t < 512) dst[t] = conds[t];
}

// ---------------- launch ----------------
extern "C" void kernel_launch(void* const* d_in, const int* in_sizes, int n_in,
                              void* d_out, int out_size) {
    const float* nodes = (const float*)d_in[0];
    const float* edges = (const float*)d_in[1];
    const float* conds = (const float*)d_in[2];
    const float* Wqkv = (const float*)d_in[3];
    const float* bqkv = (const float*)d_in[4];
    const float* Wno = (const float*)d_in[5];
    const float* bno = (const float*)d_in[6];
    const float* Weo = (const float*)d_in[7];
    const float* beo = (const float*)d_in[8];
    const float* g1n = (const float*)d_in[9];
    const float* b1n = (const float*)d_in[10];
    const float* g1e = (const float*)d_in[11];
    const float* b1e = (const float*)d_in[12];
    const float* Wn1 = (const float*)d_in[13];
    const float* bn1 = (const float*)d_in[14];
    const float* Wn2 = (const float*)d_in[15];
    const float* bn2 = (const float*)d_in[16];
    const float* We1 = (const float*)d_in[17];
    const float* be1 = (const float*)d_in[18];
    const float* We2 = (const float*)d_in[19];
    const float* be2 = (const float*)d_in[20];
    const float* g2n = (const float*)d_in[21];
    const float* b2n = (const float*)d_in[22];
    const float* g2e = (const float*)d_in[23];
    const float* b2e = (const float*)d_in[24];

    float* out = (float*)d_out;
    float* out_nodes = out;
    float* out_edges = out + 131072;
    float* out_conds = out + 131072 + 33554432;

    cudaFuncSetAttribute(edge_tc, cudaFuncAttributeMaxDynamicSharedMemorySize, DSMEM);

    prep_kernel<<<1024, 256>>>(Weo, We1, We2);
    qkv_kernel<<<512, 256>>>(nodes, conds, Wqkv, bqkv);
    attn_kernel<<<512, 256>>>(edges, nodes, Wno, bno, g1n, b1n);
    nodemlp_kernel<<<512, 256>>>(Wn1, bn1, Wn2, bn2, g2n, b2n, out_nodes);
    edge_tc<<<2048, 256, DSMEM>>>(edges, beo, g1e, b1e, be1, be2, g2e, b2e, out_edges);
    copy_conds<<<2, 256>>>(conds, out_conds);
}

// round 14
// speedup vs baseline: 1.6503x; 1.6503x over previous
#include <cuda_runtime.h>
#include <cuda_bf16.h>
#include <mma.h>
#include <cstdint>
#include <cstddef>

using namespace nvcuda;

#define SCALE 0.0625f
#define EPSLN 1e-5f

// edge_tc smem byte offsets (R6 winner layout)
#define OFF_A1H 0
#define OFF_A1L 33792
#define OFF_HH 67584
#define OFF_HL 101376
#define OFF_BH 135168
#define OFF_BL 172032
#define OFF_QS 208896
#define DSMEM 209920
#define LDA 264  // bf16 elems per row in A/H tiles
#define LDB 72   // bf16 elems per row in B stage
#define LDC 260  // f32 elems per row in Cstage (aliases B at OFF_BH)

typedef wmma::fragment<wmma::matrix_a, 16, 16, 16, __nv_bfloat16, wmma::row_major> FragA;
typedef wmma::fragment<wmma::matrix_b, 16, 16, 16, __nv_bfloat16, wmma::col_major> FragB;
typedef wmma::fragment<wmma::accumulator, 16, 16, 16, float> FragC;

// ---------------- device scratch ----------------
__device__ float d_WqkvT[256 * 768];
__device__ float d_WnoT[256 * 256];
__device__ float d_Wn1T[256 * 1024];
__device__ float d_Wn2T[1024 * 256];
__device__ float d_q[131072];
__device__ float d_k[131072];
__device__ float d_v[131072];
__device__ float d_an1[131072];
__device__ unsigned short g_WeoH[65536], g_WeoL[65536];    // [256 n][256 k] row-major
__device__ unsigned short g_We1H[262144], g_We1L[262144];  // [1024][256]
__device__ unsigned short g_We2H[262144], g_We2L[262144];  // [256][1024]

__device__ __forceinline__ void split_w(float v, unsigned short* h, unsigned short* l) {
    __nv_bfloat16 hb = __float2bfloat16(v);
    *h = __bfloat16_as_ushort(hb);
    *l = __bfloat16_as_ushort(__float2bfloat16(v - __bfloat162float(hb)));
}
__device__ __forceinline__ void split_sm(char* smp, int off, int r, int c, float v) {
    __nv_bfloat16 hb = __float2bfloat16(v);
    *(unsigned short*)(smp + off + (r * LDA + c) * 2) = __bfloat16_as_ushort(hb);
    *(unsigned short*)(smp + off + 33792 + (r * LDA + c) * 2) =
        __bfloat16_as_ushort(__float2bfloat16(v - __bfloat162float(hb)));
}

// ---------------- prep: node transposes + edge-weight bf16 hi/lo split ----------------
__global__ void prep_kernel(const float* __restrict__ Wqkv, const float* __restrict__ Wno,
                            const float* __restrict__ Weo, const float* __restrict__ Wn1,
                            const float* __restrict__ Wn2, const float* __restrict__ We1,
                            const float* __restrict__ We2) {
    int idx = blockIdx.x * 256 + threadIdx.x;  // 262144 total
    if (idx < 196608) { int r = idx >> 8, c = idx & 255; d_WqkvT[c * 768 + r] = Wqkv[idx]; }
    if (idx < 65536) {
        int r = idx >> 8, c = idx & 255;
        d_WnoT[c * 256 + r] = Wno[idx];
        split_w(Weo[idx], &g_WeoH[idx], &g_WeoL[idx]);
    }
    if (idx < 262144) {
        { int r = idx >> 8, c = idx & 255; d_Wn1T[c * 1024 + r] = Wn1[idx]; }
        { int r = idx >> 10, c = idx & 1023; d_Wn2T[c * 256 + r] = Wn2[idx]; }
        split_w(We1[idx], &g_We1H[idx], &g_We1L[idx]);
        split_w(We2[idx], &g_We2H[idx], &g_We2L[idx]);
    }
}

// ---------------- qkv projection (transposed weights, coalesced) ----------------
__global__ void __launch_bounds__(256) qkv_kernel(const float* __restrict__ nodes,
                                                  const float* __restrict__ conds,
                                                  const float* __restrict__ bqkv) {
    __shared__ float x[256];
    int bi = blockIdx.x, b = bi >> 8, t = threadIdx.x;
    x[t] = nodes[bi * 256 + t] + conds[(b << 8) + t];
    __syncthreads();
#pragma unroll
    for (int s = 0; s < 3; s++) {
        int o = t + (s << 8);
        float acc = bqkv[o];
#pragma unroll 8
        for (int c = 0; c < 256; c++) acc += x[c] * d_WqkvT[c * 768 + o];
        float* dst = (s == 0) ? d_q : (s == 1) ? d_k : d_v;
        dst[bi * 256 + t] = acc;
    }
}

// ---------------- attn: logits (unroll-4 loads) -> softmax -> WV -> Wno -> LN1 ----------------
__global__ void __launch_bounds__(256) attn_kernel(const float* __restrict__ edges,
                                                   const float* __restrict__ nodes,
                                                   const float* __restrict__ bno,
                                                   const float* __restrict__ g1n,
                                                   const float* __restrict__ b1n) {
    __shared__ float qs[256];
    __shared__ float lg[8 * 256];
    __shared__ float wv[256];
    __shared__ float red[20];
    int bi = blockIdx.x, b = bi >> 8, t = threadIdx.x, w = t >> 5, lane = t & 31;
    qs[t] = d_q[bi * 256 + t] * SCALE;
    __syncthreads();
    const float* erow = edges + (size_t)bi * 65536;
    const float* kb = d_k + b * 65536;
#pragma unroll 1
    for (int j = 0; j < 256; j += 4) {
        float v0 = qs[t] * kb[(j + 0) * 256 + t] + erow[(j + 0) * 256 + t];
        float v1 = qs[t] * kb[(j + 1) * 256 + t] + erow[(j + 1) * 256 + t];
        float v2 = qs[t] * kb[(j + 2) * 256 + t] + erow[(j + 2) * 256 + t];
        float v3 = qs[t] * kb[(j + 3) * 256 + t] + erow[(j + 3) * 256 + t];
#pragma unroll
        for (int off = 16; off; off >>= 1) {
            v0 += __shfl_xor_sync(0xffffffffu, v0, off);
            v1 += __shfl_xor_sync(0xffffffffu, v1, off);
            v2 += __shfl_xor_sync(0xffffffffu, v2, off);
            v3 += __shfl_xor_sync(0xffffffffu, v3, off);
        }
        if (lane == 0) {
            lg[w * 256 + j + 0] = v0;
            lg[w * 256 + j + 1] = v1;
            lg[w * 256 + j + 2] = v2;
            lg[w * 256 + j + 3] = v3;
        }
    }
    __syncthreads();
    {
        float m = -1e30f;
        for (int j = lane; j < 256; j += 32) m = fmaxf(m, lg[w * 256 + j]);
#pragma unroll
        for (int off = 16; off; off >>= 1) m = fmaxf(m, __shfl_xor_sync(0xffffffffu, m, off));
        float s = 0.f;
        for (int j = lane; j < 256; j += 32) {
            float e = __expf(lg[w * 256 + j] - m);
            lg[w * 256 + j] = e; s += e;
        }
#pragma unroll
        for (int off = 16; off; off >>= 1) s += __shfl_xor_sync(0xffffffffu, s, off);
        float inv = 1.f / s;
        for (int j = lane; j < 256; j += 32) lg[w * 256 + j] *= inv;
    }
    __syncthreads();
    const float* vb = d_v + b * 65536;
    float acc = 0.f;
#pragma unroll 4
    for (int j = 0; j < 256; j++) acc += lg[w * 256 + j] * vb[j * 256 + t];
    wv[t] = acc;
    __syncthreads();
    float a = bno[t];
#pragma unroll 8
    for (int c = 0; c < 256; c++) a += wv[c] * d_WnoT[c * 256 + t];
    a += nodes[bi * 256 + t];
    float s1 = a, s2 = a * a;
#pragma unroll
    for (int off = 16; off; off >>= 1) {
        s1 += __shfl_xor_sync(0xffffffffu, s1, off);
        s2 += __shfl_xor_sync(0xffffffffu, s2, off);
    }
    if (lane == 0) { red[w] = s1; red[8 + w] = s2; }
    __syncthreads();
    if (t == 0) {
        float a1 = 0.f, a2 = 0.f;
        for (int x = 0; x < 8; x++) { a1 += red[x]; a2 += red[8 + x]; }
        float m = a1 * (1.f / 256.f);
        red[16] = m;
        red[17] = rsqrtf(a2 * (1.f / 256.f) - m * m + EPSLN);
    }
    __syncthreads();
    d_an1[bi * 256 + t] = (a - red[16]) * red[17] * g1n[t] + b1n[t];
}

// ---------------- node MLP (transposed weights, coalesced) ----------------
__global__ void __launch_bounds__(256) nodemlp_kernel(const float* __restrict__ bn1,
                                                      const float* __restrict__ bn2,
                                                      const float* __restrict__ g2n,
                                                      const float* __restrict__ b2n,
                                                      float* __restrict__ out_nodes) {
    __shared__ float a[256];
    __shared__ float h[1024];
    __shared__ float red[20];
    int bi = blockIdx.x, t = threadIdx.x, w = t >> 5, lane = t & 31;
    a[t] = d_an1[bi * 256 + t];
    __syncthreads();
#pragma unroll
    for (int s = 0; s < 4; s++) {
        int m = t + (s << 8);
        float acc = bn1[m];
#pragma unroll 8
        for (int e = 0; e < 256; e++) acc += a[e] * d_Wn1T[e * 1024 + m];
        h[m] = fmaxf(acc, 0.f);
    }
    __syncthreads();
    float o = bn2[t];
#pragma unroll 8
    for (int m = 0; m < 1024; m++) o += h[m] * d_Wn2T[m * 256 + t];
    float v = o + a[t];
    float s1 = v, s2 = v * v;
#pragma unroll
    for (int off = 16; off; off >>= 1) {
        s1 += __shfl_xor_sync(0xffffffffu, s1, off);
        s2 += __shfl_xor_sync(0xffffffffu, s2, off);
    }
    if (lane == 0) { red[w] = s1; red[8 + w] = s2; }
    __syncthreads();
    if (t == 0) {
        float a1 = 0.f, a2 = 0.f;
        for (int x = 0; x < 8; x++) { a1 += red[x]; a2 += red[8 + x]; }
        float m = a1 * (1.f / 256.f);
        red[16] = m;
        red[17] = rsqrtf(a2 * (1.f / 256.f) - m * m + EPSLN);
    }
    __syncthreads();
    out_nodes[bi * 256 + t] = (v - red[16]) * red[17] * g2n[t] + b2n[t];
}

// ---------------- edge pipeline: R6 winner, byte-identical ----------------
__device__ __forceinline__ void stageB(char* smp, const unsigned short* __restrict__ WH,
                                       const unsigned short* __restrict__ WL, int wp,
                                       int kbase, int t) {
#pragma unroll
    for (int i = 0; i < 8; i++) {
        int idx = t + i * 256;
        int row = idx >> 3, seg = idx & 7;
        *((uint4*)(smp + OFF_BH + row * 144) + seg) =
            *((const uint4*)(WH + (size_t)row * wp + kbase) + seg);
        *((uint4*)(smp + OFF_BL + row * 144) + seg) =
            *((const uint4*)(WL + (size_t)row * wp + kbase) + seg);
    }
}

__device__ __forceinline__ void mma_chunk(const char* smp, int aoff, FragC acc[2][4],
                                          int mg, int ng, int kc) {
    const __nv_bfloat16* Ahi = (const __nv_bfloat16*)(smp + aoff);
    const __nv_bfloat16* Alo = (const __nv_bfloat16*)(smp + aoff + 33792);
    const __nv_bfloat16* Bhi = (const __nv_bfloat16*)(smp + OFF_BH);
    const __nv_bfloat16* Blo = (const __nv_bfloat16*)(smp + OFF_BL);
#pragma unroll
    for (int ks = 0; ks < 4; ks++) {
        int col = kc * 64 + ks * 16;
        FragA ah[2], al[2];
#pragma unroll
        for (int mi = 0; mi < 2; mi++) {
            int row0 = mg * 32 + mi * 16;
            wmma::load_matrix_sync(ah[mi], Ahi + row0 * LDA + col, LDA);
            wmma::load_matrix_sync(al[mi], Alo + row0 * LDA + col, LDA);
        }
#pragma unroll
        for (int ns = 0; ns < 4; ns++) {
            int n0 = ng * 64 + ns * 16;
            FragB bh, bl;
            wmma::load_matrix_sync(bh, Bhi + n0 * LDB + ks * 16, LDB);
            wmma::load_matrix_sync(bl, Blo + n0 * LDB + ks * 16, LDB);
#pragma unroll
            for (int mi = 0; mi < 2; mi++) {
                wmma::mma_sync(acc[mi][ns], ah[mi], bh, acc[mi][ns]);
                wmma::mma_sync(acc[mi][ns], ah[mi], bl, acc[mi][ns]);
                wmma::mma_sync(acc[mi][ns], al[mi], bh, acc[mi][ns]);
            }
        }
    }
}

__device__ __forceinline__ void storeC(char* smp, FragC acc[2][4], int mg, int ng) {
    float* C = (float*)(smp + OFF_BH);
#pragma unroll
    for (int mi = 0; mi < 2; mi++)
#pragma unroll
        for (int ns = 0; ns < 4; ns++)
            wmma::store_matrix_sync(C + (mg * 32 + mi * 16) * LDC + ng * 64 + ns * 16,
                                    acc[mi][ns], LDC, wmma::mem_row_major);
}

__global__ void __launch_bounds__(256) edge_tc(const float* __restrict__ edges,
                                               const float* __restrict__ beo,
                                               const float* __restrict__ g1e,
                                               const float* __restrict__ b1e,
                                               const float* __restrict__ be1,
                                               const float* __restrict__ be2,
                                               const float* __restrict__ g2e,
                                               const float* __restrict__ b2e,
                                               float* __restrict__ out_edges) {
    extern __shared__ char smp[];
    const int t = threadIdx.x, w = t >> 5;
    const int mg = w >> 2, ng = w & 3;
    const int blk = blockIdx.x;           // 0..2047, 64 rows each
    const int bi = blk >> 2;              // b*256+i
    const int b = bi >> 8;
    const int j0 = (blk & 3) << 6;
    const size_t rowbase = (size_t)blk * 64;
    const int r = t >> 2, sub = t & 3;    // epilogue mapping: 4 threads/row
    float* Cst = (float*)(smp + OFF_BH);

    // ---- T = q*k*scale + e -> split into A1 tiles ----
    float* qs = (float*)(smp + OFF_QS);
    qs[t] = d_q[bi * 256 + t];
    __syncthreads();
    const float* ebase = edges + rowbase * 256;
    const float* kbase = d_k + ((size_t)(b << 8) + j0) * 256;
#pragma unroll 4
    for (int idx = t; idx < 16384; idx += 256) {
        int rr = idx >> 8, c = idx & 255;
        split_sm(smp, OFF_A1H, rr, c, qs[c] * SCALE * kbase[idx] + ebase[idx]);
    }

    // ---- G1: C = T @ Weo^T ----
    FragC acc1[2][4];
#pragma unroll
    for (int mi = 0; mi < 2; mi++)
#pragma unroll
        for (int ns = 0; ns < 4; ns++) wmma::fill_fragment(acc1[mi][ns], 0.f);
    for (int kc = 0; kc < 4; kc++) {
        __syncthreads();
        stageB(smp, g_WeoH, g_WeoL, 256, kc * 64, t);
        __syncthreads();
        mma_chunk(smp, OFF_A1H, acc1, mg, ng, kc);
    }
    __syncthreads();
    storeC(smp, acc1, mg, ng);
    __syncthreads();

    // ---- Epi1: v = relu(C+beo)+e ; LN -> A1 ----
    {
        float s1 = 0.f, s2 = 0.f;
        const float* erow = edges + (rowbase + r) * 256;
        float* Crow = Cst + r * LDC;
#pragma unroll 4
        for (int i = 0; i < 64; i++) {
            int c = sub * 64 + i;
            float v = fmaxf(Crow[c] + beo[c], 0.f) + erow[c];
            Crow[c] = v; s1 += v; s2 += v * v;
        }
        s1 += __shfl_xor_sync(0xffffffffu, s1, 1); s2 += __shfl_xor_sync(0xffffffffu, s2, 1);
        s1 += __shfl_xor_sync(0xffffffffu, s1, 2); s2 += __shfl_xor_sync(0xffffffffu, s2, 2);
        float m = s1 * (1.f / 256.f);
        float rs = rsqrtf(s2 * (1.f / 256.f) - m * m + EPSLN);
#pragma unroll 4
        for (int i = 0; i < 64; i++) {
            int c = sub * 64 + i;
            split_sm(smp, OFF_A1H, r, c, (Crow[c] - m) * rs * g1e[c] + b1e[c]);
        }
    }

    // ---- MLP: 4 hidden chunks: G2 -> relu -> G3 accumulate ----
    FragC acc3[2][4];
#pragma unroll
    for (int mi = 0; mi < 2; mi++)
#pragma unroll
        for (int ns = 0; ns < 4; ns++) wmma::fill_fragment(acc3[mi][ns], 0.f);

    for (int nc = 0; nc < 4; nc++) {
        FragC acc2[2][4];
#pragma unroll
        for (int mi = 0; mi < 2; mi++)
#pragma unroll
            for (int ns = 0; ns < 4; ns++) wmma::fill_fragment(acc2[mi][ns], 0.f);
        for (int kc = 0; kc < 4; kc++) {
            __syncthreads();
            stageB(smp, g_We1H + nc * 65536, g_We1L + nc * 65536, 256, kc * 64, t);
            __syncthreads();
            mma_chunk(smp, OFF_A1H, acc2, mg, ng, kc);
        }
        __syncthreads();
        storeC(smp, acc2, mg, ng);
        __syncthreads();
        {   // Epi-H: H = relu(C + be1[nc*256+c])
            float* Crow = Cst + r * LDC;
#pragma unroll 4
            for (int i = 0; i < 64; i++) {
                int c = sub * 64 + i;
                split_sm(smp, OFF_HH, r, c, fmaxf(Crow[c] + be1[nc * 256 + c], 0.f));
            }
        }
        for (int kc = 0; kc < 4; kc++) {
            __syncthreads();
            stageB(smp, g_We2H, g_We2L, 1024, nc * 256 + kc * 64, t);
            __syncthreads();
            mma_chunk(smp, OFF_HH, acc3, mg, ng, kc);
        }
    }
    __syncthreads();
    storeC(smp, acc3, mg, ng);
    __syncthreads();

    // ---- Epi3: v = C + be2 + A1 ; LN -> out ----
    {
        float s1 = 0.f, s2 = 0.f;
        float* Crow = Cst + r * LDC;
        const unsigned short* a1h = (const unsigned short*)(smp + OFF_A1H) + r * LDA;
        const unsigned short* a1l = (const unsigned short*)(smp + OFF_A1L) + r * LDA;
#pragma unroll 4
        for (int i = 0; i < 64; i++) {
            int c = sub * 64 + i;
            float a1 = __bfloat162float(__ushort_as_bfloat16(a1h[c])) +
                       __bfloat162float(__ushort_as_bfloat16(a1l[c]));
            float v = Crow[c] + be2[c] + a1;
            Crow[c] = v; s1 += v; s2 += v * v;
        }
        s1 += __shfl_xor_sync(0xffffffffu, s1, 1); s2 += __shfl_xor_sync(0xffffffffu, s2, 1);
        s1 += __shfl_xor_sync(0xffffffffu, s1, 2); s2 += __shfl_xor_sync(0xffffffffu, s2, 2);
        float m = s1 * (1.f / 256.f);
        float rs = rsqrtf(s2 * (1.f / 256.f) - m * m + EPSLN);
        float* orow = out_edges + (rowbase + r) * 256;
#pragma unroll 4
        for (int i = 0; i < 64; i++) {
            int c = sub * 64 + i;
            orow[c] = (Crow[c] - m) * rs * g2e[c] + b2e[c];
        }
    }
}

__global__ void copy_conds(const float* __restrict__ conds, float* __restrict__ dst) {
    int t = blockIdx.x * 256 + threadIdx.x;
    if (t < 512) dst[t] = conds[t];
}

// ---------------- launch (edge_tc is 4th so ncu captures it) ----------------
extern "C" void kernel_launch(void* const* d_in, const int* in_sizes, int n_in,
                              void* d_out, int out_size) {
    const float* nodes = (const float*)d_in[0];
    const float* edges = (const float*)d_in[1];
    const float* conds = (const float*)d_in[2];
    const float* Wqkv = (const float*)d_in[3];
    const float* bqkv = (const float*)d_in[4];
    const float* Wno = (const float*)d_in[5];
    const float* bno = (const float*)d_in[6];
    const float* Weo = (const float*)d_in[7];
    const float* beo = (const float*)d_in[8];
    const float* g1n = (const float*)d_in[9];
    const float* b1n = (const float*)d_in[10];
    const float* g1e = (const float*)d_in[11];
    const float* b1e = (const float*)d_in[12];
    const float* Wn1 = (const float*)d_in[13];
    const float* bn1 = (const float*)d_in[14];
    const float* Wn2 = (const float*)d_in[15];
    const float* bn2 = (const float*)d_in[16];
    const float* We1 = (const float*)d_in[17];
    const float* be1 = (const float*)d_in[18];
    const float* We2 = (const float*)d_in[19];
    const float* be2 = (const float*)d_in[20];
    const float* g2n = (const float*)d_in[21];
    const float* b2n = (const float*)d_in[22];
    const float* g2e = (const float*)d_in[23];
    const float* b2e = (const float*)d_in[24];

    float* out = (float*)d_out;
    float* out_nodes = out;
    float* out_edges = out + 131072;
    float* out_conds = out + 131072 + 33554432;

    cudaFuncSetAttribute(edge_tc, cudaFuncAttributeMaxDynamicSharedMemorySize, DSMEM);

    prep_kernel<<<1024, 256>>>(Wqkv, Wno, Weo, Wn1, Wn2, We1, We2);
    qkv_kernel<<<512, 256>>>(nodes, conds, bqkv);
    attn_kernel<<<512, 256>>>(edges, nodes, bno, g1n, b1n);
    edge_tc<<<2048, 256, DSMEM>>>(edges, beo, g1e, b1e, be1, be2, g2e, b2e, out_edges);
    nodemlp_kernel<<<512, 256>>>(bn1, bn2, g2n, b2n, out_nodes);
    copy_conds<<<2, 256>>>(conds, out_conds);
}